// round 14
// baseline (speedup 1.0000x reference)
#include <cuda_runtime.h>
#include <cuda_bf16.h>
#include <cstdint>

// Problem constants
#define Bb 16
#define Nn 577
#define Cc 768
#define Hh 12
#define Dd 64
#define SCALEF 0.125f
#define ALPHAF 0.1f
#define MM (Bb * Nn)        // 9232
#define QKVN (3 * Cc)       // 2304
#define KDIM 768
#define NPATCH (Nn - 1)     // 576

#define NX  (MM * KDIM)
#define NWQ (KDIM * QKVN)
#define NWP (KDIM * Cc)

// Device-global scratch (referenced ONLY from device code — GB300 ATS
// silently dereferences host shadows passed as kernel args; R8/R9 bug).
__device__ __nv_bfloat16 g_xh[NX],  g_xl[NX];
__device__ __nv_bfloat16 g_wqh[NWQ], g_wql[NWQ];
__device__ __nv_bfloat16 g_wph[NWP], g_wpl[NWP];
__device__ __nv_bfloat16 g_qh[Bb * Hh * Nn * Dd], g_ql[Bb * Hh * Nn * Dd];
__device__ __nv_bfloat16 g_kh[Bb * Hh * Nn * Dd], g_kl[Bb * Hh * Nn * Dd];
__device__ __nv_bfloat16 g_vh[Bb * Hh * Nn * Dd], g_vl[Bb * Hh * Nn * Dd];
__device__ __nv_bfloat16 g_aoh[MM * Cc], g_aol[MM * Cc];

// ===========================================================================
// Helpers
// ===========================================================================
__device__ __forceinline__ uint32_t smem_u32(const void* p) {
    return (uint32_t)__cvta_generic_to_shared(p);
}
__device__ __forceinline__ void ldsm4(uint32_t r[4], uint32_t addr) {
    asm volatile("ldmatrix.sync.aligned.m8n8.x4.shared.b16 {%0,%1,%2,%3}, [%4];"
        : "=r"(r[0]), "=r"(r[1]), "=r"(r[2]), "=r"(r[3]) : "r"(addr));
}
__device__ __forceinline__ void ldsm4t(uint32_t r[4], uint32_t addr) {
    asm volatile("ldmatrix.sync.aligned.m8n8.x4.trans.shared.b16 {%0,%1,%2,%3}, [%4];"
        : "=r"(r[0]), "=r"(r[1]), "=r"(r[2]), "=r"(r[3]) : "r"(addr));
}
__device__ __forceinline__ void mma16816(float c[4], const uint32_t a[4],
                                         uint32_t b0, uint32_t b1) {
    asm volatile(
        "mma.sync.aligned.m16n8k16.row.col.f32.bf16.bf16.f32 "
        "{%0,%1,%2,%3}, {%4,%5,%6,%7}, {%8,%9}, {%0,%1,%2,%3};"
        : "+f"(c[0]), "+f"(c[1]), "+f"(c[2]), "+f"(c[3])
        : "r"(a[0]), "r"(a[1]), "r"(a[2]), "r"(a[3]), "r"(b0), "r"(b1));
}
__device__ __forceinline__ uint32_t pack_hi(float x, float y,
                                            float& lx, float& ly) {
    __nv_bfloat16 hx = __float2bfloat16(x);
    __nv_bfloat16 hy = __float2bfloat16(y);
    lx = x - __bfloat162float(hx);
    ly = y - __bfloat162float(hy);
    __nv_bfloat162 p{hx, hy};
    return *(uint32_t*)&p;
}
__device__ __forceinline__ uint32_t pack_bf2(float x, float y) {
    __nv_bfloat162 p{__float2bfloat16(x), __float2bfloat16(y)};
    return *(uint32_t*)&p;
}
__device__ __forceinline__ void split1(float v, __nv_bfloat16& h, __nv_bfloat16& l) {
    h = __float2bfloat16(v);
    l = __float2bfloat16(v - __bfloat162float(h));
}
__device__ __forceinline__ void cp16(uint32_t dst, const void* src, bool pred) {
    int sz = pred ? 16 : 0;
    asm volatile("cp.async.cg.shared.global [%0], [%1], 16, %2;"
                 :: "r"(dst), "l"(src), "r"(sz));
}
__device__ __forceinline__ void cp_commit() {
    asm volatile("cp.async.commit_group;");
}
__device__ __forceinline__ void cp_wait1() {
    asm volatile("cp.async.wait_group 1;");
}
__device__ __forceinline__ void cp_wait2() {
    asm volatile("cp.async.wait_group 2;");
}

extern __shared__ unsigned char dynsm[];

// ===========================================================================
// Pre-split: x, w_qkv, w_proj -> bf16 hi/lo
// ===========================================================================
__global__ __launch_bounds__(256) void split_all(
    const float* __restrict__ x,
    const float* __restrict__ wq,
    const float* __restrict__ wp)
{
    long i = ((long)blockIdx.x * 256 + threadIdx.x) * 4;
    const float* src;
    __nv_bfloat16 *dh, *dl;
    long o;
    if (i < NX)                 { src = x;  dh = g_xh;  dl = g_xl;  o = i; }
    else if (i < NX + NWQ)      { src = wq; dh = g_wqh; dl = g_wql; o = i - NX; }
    else if (i < NX + NWQ + NWP){ src = wp; dh = g_wph; dl = g_wpl; o = i - NX - NWQ; }
    else return;
    float4 f = *(const float4*)(src + o);
    __nv_bfloat16 h0, h1, h2, h3, l0, l1, l2, l3;
    split1(f.x, h0, l0); split1(f.y, h1, l1);
    split1(f.z, h2, l2); split1(f.w, h3, l3);
    __nv_bfloat162 ph0{h0, h1}, ph1{h2, h3}, pl0{l0, l1}, pl1{l2, l3};
    *(uint2*)(dh + o) = make_uint2(*(uint32_t*)&ph0, *(uint32_t*)&ph1);
    *(uint2*)(dl + o) = make_uint2(*(uint32_t*)&pl0, *(uint32_t*)&pl1);
}

// ===========================================================================
// Split-bf16 tensor GEMM, cp.async 4-stage pipeline (3 tiles in flight).
// ===========================================================================
#define APITCH 40
#define BPITCH 136
#define STAGE_ELEMS (128 * APITCH * 2 + 32 * BPITCH * 2)
#define STAGE_BYTES (STAGE_ELEMS * 2)      // 37888
#define NSTAGE 4
#define GEMM_SMEM (NSTAGE * STAGE_BYTES)   // 151552

template <int EPI>
__global__ __launch_bounds__(256) void gemm_pipe(
    const float* __restrict__ bias,
    float* __restrict__ out)
{
    constexpr int LDB = EPI ? Cc : QKVN;
    constexpr int NT  = KDIM / 32;  // 24
    const __nv_bfloat16* Ah = EPI ? g_aoh : g_xh;
    const __nv_bfloat16* Al = EPI ? g_aol : g_xl;
    const __nv_bfloat16* Bh = EPI ? g_wph : g_wqh;
    const __nv_bfloat16* Bl = EPI ? g_wpl : g_wql;

    const int tid  = threadIdx.x;
    const int lane = tid & 31, warp = tid >> 5;
    const int rowBase = blockIdx.y * 128;
    const int colBase = blockIdx.x * 128;
    const int wm0 = (warp >> 2) * 64;
    const int wn0 = (warp & 3) * 32;
    const uint32_t smemBase = smem_u32(dynsm);

    auto issue_tile = [&](int tile) {
        if (tile >= NT) { cp_commit(); return; }
        const int k0 = tile * 32;
        const uint32_t sb = smemBase + (tile % NSTAGE) * STAGE_BYTES;
#pragma unroll
        for (int rep = 0; rep < 2; rep++) {
            const int g = tid + rep * 256;
            const int row = g >> 2, kc = g & 3;
            const int gr = rowBase + row;
            const bool ok = gr < MM;
            const long so = (long)(ok ? gr : 0) * KDIM + k0 + kc * 8;
            const uint32_t d = sb + (row * APITCH + kc * 8) * 2;
            cp16(d,                    Ah + so, ok);
            cp16(d + 128 * APITCH * 2, Al + so, ok);
        }
#pragma unroll
        for (int rep = 0; rep < 2; rep++) {
            const int g = tid + rep * 256;
            const int krow = g >> 4, nc = g & 15;
            const long so = (long)(k0 + krow) * LDB + colBase + nc * 8;
            const uint32_t d = sb + (256 * APITCH + krow * BPITCH + nc * 8) * 2;
            cp16(d,                   Bh + so, true);
            cp16(d + 32 * BPITCH * 2, Bl + so, true);
        }
        cp_commit();
    };

    float acc[4][4][4];
#pragma unroll
    for (int mi = 0; mi < 4; mi++)
#pragma unroll
        for (int j = 0; j < 4; j++)
#pragma unroll
            for (int r = 0; r < 4; r++) acc[mi][j][r] = 0.f;

    const int aOff = (wm0 + (lane & 15)) * (APITCH * 2) + (lane >> 4) * 16;
    const int bOff = (lane & 15) * (BPITCH * 2) + (wn0 + ((lane >> 4) << 3)) * 2;

    issue_tile(0);
    issue_tile(1);
    issue_tile(2);

#pragma unroll 1
    for (int t = 0; t < NT; t++) {
        cp_wait2();          // tile t complete (groups t+1, t+2 may be pending)
        __syncthreads();     // visibility + all warps done reading stage (t+3)%4
        issue_tile(t + 3);   // empty commit past the end keeps accounting uniform

        const uint32_t base = smemBase + (t % NSTAGE) * STAGE_BYTES;
        const uint32_t aHiB = base + aOff;
        const uint32_t aLoB = aHiB + 128 * APITCH * 2;
        const uint32_t bHiB = base + 256 * APITCH * 2 + bOff;
        const uint32_t bLoB = bHiB + 32 * BPITCH * 2;

#pragma unroll
        for (int ks = 0; ks < 2; ks++) {
            uint32_t ah[4][4], al[4][4], bh[2][4], bl[2][4];
#pragma unroll
            for (int mi = 0; mi < 4; mi++) {
                ldsm4(ah[mi], aHiB + mi * (16 * APITCH * 2) + ks * 32);
                ldsm4(al[mi], aLoB + mi * (16 * APITCH * 2) + ks * 32);
            }
#pragma unroll
            for (int nb = 0; nb < 2; nb++) {
                ldsm4t(bh[nb], bHiB + nb * 32 + ks * (16 * BPITCH * 2));
                ldsm4t(bl[nb], bLoB + nb * 32 + ks * (16 * BPITCH * 2));
            }
#pragma unroll
            for (int mi = 0; mi < 4; mi++)
#pragma unroll
                for (int j = 0; j < 4; j++) {
                    const int nb = j >> 1, hf = (j & 1) * 2;
                    mma16816(acc[mi][j], ah[mi], bh[nb][hf], bh[nb][hf + 1]);
                    mma16816(acc[mi][j], ah[mi], bl[nb][hf], bl[nb][hf + 1]);
                    mma16816(acc[mi][j], al[mi], bh[nb][hf], bh[nb][hf + 1]);
                }
        }
    }

    // ---- epilogue ----
#pragma unroll
    for (int mi = 0; mi < 4; mi++) {
        const int r0 = wm0 + mi * 16 + (lane >> 2);
#pragma unroll
        for (int half = 0; half < 2; half++) {
            const int gr = rowBase + r0 + half * 8;
            if (gr >= MM) continue;
            if (EPI == 0) {
                const int bidx = gr / Nn, n = gr % Nn;
#pragma unroll
                for (int j = 0; j < 4; j++) {
                    const int c0 = wn0 + j * 8 + (lane & 3) * 2;
#pragma unroll
                    for (int e = 0; e < 2; e++) {
                        const int gc = colBase + c0 + e;
                        float v = acc[mi][j][half * 2 + e] + bias[gc];
                        const int which = gc / Cc;
                        const int cc = gc % Cc;
                        const int h = cc >> 6, d = cc & 63;
                        const long base = (((long)bidx * Hh + h) * Nn + n) * Dd + d;
                        __nv_bfloat16 hh, ll;
                        split1(v, hh, ll);
                        if (which == 0)      { g_qh[base] = hh; g_ql[base] = ll; }
                        else if (which == 1) { g_kh[base] = hh; g_kl[base] = ll; }
                        else                 { g_vh[base] = hh; g_vl[base] = ll; }
                    }
                }
            } else {
#pragma unroll
                for (int j = 0; j < 4; j++) {
                    const int c0 = wn0 + j * 8 + (lane & 3) * 2;
                    const int gc = colBase + c0;
                    float2 v2 = make_float2(acc[mi][j][half * 2 + 0] + bias[gc],
                                            acc[mi][j][half * 2 + 1] + bias[gc + 1]);
                    *(float2*)&out[(long)gr * Cc + gc] = v2;
                }
            }
        }
    }
}

// ===========================================================================
// Tensor-core flash attention, cp.async double-buffered K/V chunks.
// Smem: Q region 36864 B + 2 chunk buffers (36864 B each) = 110592 B.
// Chunk buffer layout (bytes): Khi +0, Klo +9216, Vhi +18432, Vlo +27648.
// ===========================================================================
#define QT 128
#define KT 64
#define NQT ((Nn + QT - 1) / QT)   // 5
#define NKT ((Nn + KT - 1) / KT)   // 10
#define QP 72
#define QREG_BYTES (2 * QT * QP * 2)   // 36864
#define CHUNK_BYTES (4 * KT * QP * 2)  // 36864
#define ATTN_SMEM (QREG_BYTES + 2 * CHUNK_BYTES)  // 110592

__global__ __launch_bounds__(256) void attn_mma(
    const float* __restrict__ aw,
    float* __restrict__ patch)
{
    __nv_bfloat16* sm = (__nv_bfloat16*)dynsm;
    __nv_bfloat16* Qhi = sm;
    __nv_bfloat16* Qlo = sm + QT * QP;

    const int bh = blockIdx.y;
    const int b  = bh / Hh;
    const int h  = bh % Hh;
    const int qt = blockIdx.x;
    const int n0 = qt * QT;
    const int NQ = min(QT, Nn - n0);

    const int tid  = threadIdx.x;
    const int lane = tid & 31, warp = tid >> 5;
    const uint32_t smBase = smem_u32(dynsm);

    auto issue_chunk = [&](int ch) {
        if (ch >= NKT) { cp_commit(); return; }
        const int kc0 = ch * KT;
        const uint32_t bb = smBase + QREG_BYTES + (ch & 1) * CHUNK_BYTES;
#pragma unroll
        for (int rep = 0; rep < 2; rep++) {
            const int g = tid + rep * 256;        // 512 granules per array
            const int c = g >> 3, q = g & 7;      // row, 16B-unit
            const bool ok = (kc0 + c) < Nn;
            const long gb = ((long)bh * Nn + (ok ? kc0 + c : 0)) * Dd + q * 8;
            const uint32_t de = (uint32_t)(c * QP + q * 8) * 2;
            cp16(bb + de,         g_kh + gb, ok);
            cp16(bb + 9216 + de,  g_kl + gb, ok);
            cp16(bb + 18432 + de, g_vh + gb, ok);
            cp16(bb + 27648 + de, g_vl + gb, ok);
        }
        cp_commit();
    };

    // ---- stage Q tile (hi/lo straight copy) ----
    {
        const int r = tid >> 1;
        const int half = tid & 1;
        const bool valid = (r < NQ);
        const long gb = ((long)bh * Nn + n0 + (valid ? r : 0)) * Dd;
        const uint4* sh = (const uint4*)(g_qh + gb) + half * 4;
        const uint4* sl = (const uint4*)(g_ql + gb) + half * 4;
        uint4* dh = (uint4*)(Qhi + r * QP + half * 32);
        uint4* dl = (uint4*)(Qlo + r * QP + half * 32);
        const uint4 z = make_uint4(0, 0, 0, 0);
#pragma unroll
        for (int i = 0; i < 4; i++) {
            dh[i] = valid ? sh[i] : z;
            dl[i] = valid ? sl[i] : z;
        }
    }
    issue_chunk(0);          // overlap chunk-0 copy with Q fragment setup
    __syncthreads();

    // ---- Q fragments to registers ----
    uint32_t qh[4][4], ql[4][4];
    {
        const uint32_t qLane = ((warp << 4) + (lane & 15)) * (QP * 2) + (lane >> 4) * 16;
        const uint32_t QhiB = smem_u32(Qhi) + qLane;
        const uint32_t QloB = smem_u32(Qlo) + qLane;
#pragma unroll
        for (int ks = 0; ks < 4; ks++) {
            ldsm4(qh[ks], QhiB + ks * 32);
            ldsm4(ql[ks], QloB + ks * 32);
        }
    }

    float m_lo = -1e30f, m_hi = -1e30f, l_lo = 0.f, l_hi = 0.f;
    float o[8][4];
#pragma unroll
    for (int nt = 0; nt < 8; nt++)
#pragma unroll
        for (int e = 0; e < 4; e++) o[nt][e] = 0.f;

    const uint32_t fragLane = (lane & 15) * (QP * 2) + (lane >> 4) * 16;
    const int cbase = 2 * (lane & 3);
    const bool clsLane = (qt == 0) && (warp == 0) && ((lane >> 2) == 0);

#pragma unroll 1
    for (int ch = 0; ch < NKT; ch++) {
        const int kc0 = ch * KT;
        const int KC  = min(KT, Nn - kc0);

        issue_chunk(ch + 1);   // next chunk copy overlaps this chunk's compute
        cp_wait1();            // chunk ch copy complete
        __syncthreads();       // smem visibility across warps

        const uint32_t bb = smBase + QREG_BYTES + (ch & 1) * CHUNK_BYTES;
        const uint32_t KhiB = bb + fragLane;
        const uint32_t KloB = bb + 9216 + fragLane;
        const uint32_t VhiB = bb + 18432 + fragLane;
        const uint32_t VloB = bb + 27648 + fragLane;

        // ---- S = Q·K^T ----
        float s[8][4];
#pragma unroll
        for (int nt = 0; nt < 8; nt++)
#pragma unroll
            for (int e = 0; e < 4; e++) s[nt][e] = 0.f;

#pragma unroll
        for (int ks = 0; ks < 4; ks++)
#pragma unroll
            for (int g = 0; g < 4; g++) {
                uint32_t kh[4], kl[4];
                const uint32_t off = g * (16 * QP * 2) + ks * 32;
                ldsm4(kh, KhiB + off);
                ldsm4(kl, KloB + off);
                mma16816(s[2 * g],     qh[ks], kh[0], kh[2]);
                mma16816(s[2 * g],     qh[ks], kl[0], kl[2]);
                mma16816(s[2 * g],     ql[ks], kh[0], kh[2]);
                mma16816(s[2 * g + 1], qh[ks], kh[1], kh[3]);
                mma16816(s[2 * g + 1], qh[ks], kl[1], kl[3]);
                mma16816(s[2 * g + 1], ql[ks], kh[1], kh[3]);
            }

        // ---- scale + mask ----
#pragma unroll
        for (int nt = 0; nt < 8; nt++)
#pragma unroll
            for (int e = 0; e < 4; e++) {
                const int c = nt * 8 + cbase + (e & 1);
                float sv = s[nt][e] * SCALEF;
                s[nt][e] = (c < KC) ? sv : -1e30f;
            }

        // ---- CLS row: patch emit + reweight ----
        if (clsLane) {
#pragma unroll
            for (int nt = 0; nt < 8; nt++)
#pragma unroll
                for (int e = 0; e < 2; e++) {
                    const int mg = kc0 + nt * 8 + cbase + e;
                    if (mg >= 1 && mg < Nn) {
                        const float sv = s[nt][e];
                        patch[(long)bh * NPATCH + mg - 1] = sv;
                        const float w = aw[(long)b * NPATCH + mg - 1];
                        s[nt][e] = sv * (w * ALPHAF + (1.0f - ALPHAF));
                    }
                }
        }

        // ---- online softmax ----
        {
            float cmlo = -1e30f, cmhi = -1e30f;
#pragma unroll
            for (int nt = 0; nt < 8; nt++) {
                cmlo = fmaxf(cmlo, fmaxf(s[nt][0], s[nt][1]));
                cmhi = fmaxf(cmhi, fmaxf(s[nt][2], s[nt][3]));
            }
#pragma unroll
            for (int off = 1; off <= 2; off <<= 1) {
                cmlo = fmaxf(cmlo, __shfl_xor_sync(0xffffffffu, cmlo, off));
                cmhi = fmaxf(cmhi, __shfl_xor_sync(0xffffffffu, cmhi, off));
            }
            const float mnlo = fmaxf(m_lo, cmlo);
            const float mnhi = fmaxf(m_hi, cmhi);
            const float flo = __expf(m_lo - mnlo);
            const float fhi = __expf(m_hi - mnhi);
            float rslo = 0.f, rshi = 0.f;
#pragma unroll
            for (int nt = 0; nt < 8; nt++) {
                s[nt][0] = __expf(s[nt][0] - mnlo); rslo += s[nt][0];
                s[nt][1] = __expf(s[nt][1] - mnlo); rslo += s[nt][1];
                s[nt][2] = __expf(s[nt][2] - mnhi); rshi += s[nt][2];
                s[nt][3] = __expf(s[nt][3] - mnhi); rshi += s[nt][3];
            }
#pragma unroll
            for (int off = 1; off <= 2; off <<= 1) {
                rslo += __shfl_xor_sync(0xffffffffu, rslo, off);
                rshi += __shfl_xor_sync(0xffffffffu, rshi, off);
            }
            l_lo = l_lo * flo + rslo;  m_lo = mnlo;
            l_hi = l_hi * fhi + rshi;  m_hi = mnhi;
#pragma unroll
            for (int nt = 0; nt < 8; nt++) {
                o[nt][0] *= flo; o[nt][1] *= flo;
                o[nt][2] *= fhi; o[nt][3] *= fhi;
            }
        }

        // ---- O += P·V ----
#pragma unroll
        for (int kt = 0; kt < 4; kt++) {
            uint32_t pa_h[4], pa_l[4];
            {
                float lx, ly;
                pa_h[0] = pack_hi(s[2 * kt][0],     s[2 * kt][1],     lx, ly);
                pa_l[0] = pack_bf2(lx, ly);
                pa_h[1] = pack_hi(s[2 * kt][2],     s[2 * kt][3],     lx, ly);
                pa_l[1] = pack_bf2(lx, ly);
                pa_h[2] = pack_hi(s[2 * kt + 1][0], s[2 * kt + 1][1], lx, ly);
                pa_l[2] = pack_bf2(lx, ly);
                pa_h[3] = pack_hi(s[2 * kt + 1][2], s[2 * kt + 1][3], lx, ly);
                pa_l[3] = pack_bf2(lx, ly);
            }
#pragma unroll
            for (int g = 0; g < 4; g++) {
                uint32_t vh[4], vl[4];
                const uint32_t off = kt * (16 * QP * 2) + g * 32;
                ldsm4t(vh, VhiB + off);
                ldsm4t(vl, VloB + off);
                mma16816(o[2 * g],     pa_h, vh[0], vh[1]);
                mma16816(o[2 * g],     pa_h, vl[0], vl[1]);
                mma16816(o[2 * g],     pa_l, vh[0], vh[1]);
                mma16816(o[2 * g + 1], pa_h, vh[2], vh[3]);
                mma16816(o[2 * g + 1], pa_h, vl[2], vl[3]);
                mma16816(o[2 * g + 1], pa_l, vh[2], vh[3]);
            }
        }
        __syncthreads();   // done reading buf[ch&1] before it's re-issued
    }

    // ---- write O normalized as bf16 hi/lo ----
    {
        const int rlo = warp * 16 + (lane >> 2);
        const float invlo = 1.0f / l_lo;
        const float invhi = 1.0f / l_hi;
#pragma unroll
        for (int nt = 0; nt < 8; nt++) {
            const int d = h * Dd + nt * 8 + cbase;
            if (rlo < NQ) {
                const long base = ((long)(b * Nn + n0 + rlo)) * Cc + d;
                float a0 = o[nt][0] * invlo, a1 = o[nt][1] * invlo;
                float lx, ly;
                uint32_t hh = pack_hi(a0, a1, lx, ly);
                *(uint32_t*)&g_aoh[base] = hh;
                *(uint32_t*)&g_aol[base] = pack_bf2(lx, ly);
            }
            if (rlo + 8 < NQ) {
                const long base = ((long)(b * Nn + n0 + rlo + 8)) * Cc + d;
                float a0 = o[nt][2] * invhi, a1 = o[nt][3] * invhi;
                float lx, ly;
                uint32_t hh = pack_hi(a0, a1, lx, ly);
                *(uint32_t*)&g_aoh[base] = hh;
                *(uint32_t*)&g_aol[base] = pack_bf2(lx, ly);
            }
        }
    }
}

// ---------------------------------------------------------------------------
extern "C" void kernel_launch(void* const* d_in, const int* in_sizes, int n_in,
                              void* d_out, int out_size)
{
    const float* x      = (const float*)d_in[0];
    const float* aw     = (const float*)d_in[1];
    const float* w_qkv  = (const float*)d_in[2];
    const float* b_qkv  = (const float*)d_in[3];
    const float* w_proj = (const float*)d_in[4];
    const float* b_proj = (const float*)d_in[5];

    float* out   = (float*)d_out;
    float* patch = out + (long)Bb * Nn * Cc;

    // >48KB dynamic smem: opt in every call (no static guards).
    cudaFuncSetAttribute(gemm_pipe<0>, cudaFuncAttributeMaxDynamicSharedMemorySize, GEMM_SMEM);
    cudaFuncSetAttribute(gemm_pipe<1>, cudaFuncAttributeMaxDynamicSharedMemorySize, GEMM_SMEM);
    cudaFuncSetAttribute(attn_mma, cudaFuncAttributeMaxDynamicSharedMemorySize, ATTN_SMEM);

    const long nsplit = ((long)NX + NWQ + NWP) / 4;
    split_all<<<(unsigned)((nsplit + 255) / 256), 256>>>(x, w_qkv, w_proj);

    dim3 gq(QKVN / 128, (MM + 127) / 128);     // 18 x 73
    gemm_pipe<0><<<gq, 256, GEMM_SMEM>>>(b_qkv, nullptr);

    dim3 ga(NQT, Bb * Hh);                     // 5 x 192
    attn_mma<<<ga, 256, ATTN_SMEM>>>(aw, patch);

    dim3 gp(Cc / 128, (MM + 127) / 128);       // 6 x 73
    gemm_pipe<1><<<gp, 256, GEMM_SMEM>>>(b_proj, out);
}

// round 15
// speedup vs baseline: 1.1380x; 1.1380x over previous
#include <cuda_runtime.h>
#include <cuda_bf16.h>
#include <cstdint>

// Problem constants
#define Bb 16
#define Nn 577
#define Cc 768
#define Hh 12
#define Dd 64
#define SCALEF 0.125f
#define ALPHAF 0.1f
#define MM (Bb * Nn)        // 9232
#define QKVN (3 * Cc)       // 2304
#define KDIM 768
#define NPATCH (Nn - 1)     // 576

#define NX  (MM * KDIM)
#define NWQ (KDIM * QKVN)
#define NWP (KDIM * Cc)

// Device-global scratch (referenced ONLY from device code — GB300 ATS
// silently dereferences host shadows passed as kernel args; R8/R9 bug).
__device__ __nv_bfloat16 g_xh[NX],  g_xl[NX];
__device__ __nv_bfloat16 g_wqh[NWQ], g_wql[NWQ];
__device__ __nv_bfloat16 g_wph[NWP], g_wpl[NWP];
__device__ __nv_bfloat16 g_qh[Bb * Hh * Nn * Dd], g_ql[Bb * Hh * Nn * Dd];
__device__ __nv_bfloat16 g_kh[Bb * Hh * Nn * Dd], g_kl[Bb * Hh * Nn * Dd];
__device__ __nv_bfloat16 g_vh[Bb * Hh * Nn * Dd], g_vl[Bb * Hh * Nn * Dd];
__device__ __nv_bfloat16 g_aoh[MM * Cc], g_aol[MM * Cc];

// ===========================================================================
// Helpers
// ===========================================================================
__device__ __forceinline__ uint32_t smem_u32(const void* p) {
    return (uint32_t)__cvta_generic_to_shared(p);
}
__device__ __forceinline__ void ldsm4(uint32_t r[4], uint32_t addr) {
    asm volatile("ldmatrix.sync.aligned.m8n8.x4.shared.b16 {%0,%1,%2,%3}, [%4];"
        : "=r"(r[0]), "=r"(r[1]), "=r"(r[2]), "=r"(r[3]) : "r"(addr));
}
__device__ __forceinline__ void ldsm4t(uint32_t r[4], uint32_t addr) {
    asm volatile("ldmatrix.sync.aligned.m8n8.x4.trans.shared.b16 {%0,%1,%2,%3}, [%4];"
        : "=r"(r[0]), "=r"(r[1]), "=r"(r[2]), "=r"(r[3]) : "r"(addr));
}
__device__ __forceinline__ void mma16816(float c[4], const uint32_t a[4],
                                         uint32_t b0, uint32_t b1) {
    asm volatile(
        "mma.sync.aligned.m16n8k16.row.col.f32.bf16.bf16.f32 "
        "{%0,%1,%2,%3}, {%4,%5,%6,%7}, {%8,%9}, {%0,%1,%2,%3};"
        : "+f"(c[0]), "+f"(c[1]), "+f"(c[2]), "+f"(c[3])
        : "r"(a[0]), "r"(a[1]), "r"(a[2]), "r"(a[3]), "r"(b0), "r"(b1));
}
__device__ __forceinline__ uint32_t pack_hi(float x, float y,
                                            float& lx, float& ly) {
    __nv_bfloat16 hx = __float2bfloat16(x);
    __nv_bfloat16 hy = __float2bfloat16(y);
    lx = x - __bfloat162float(hx);
    ly = y - __bfloat162float(hy);
    __nv_bfloat162 p{hx, hy};
    return *(uint32_t*)&p;
}
__device__ __forceinline__ uint32_t pack_bf2(float x, float y) {
    __nv_bfloat162 p{__float2bfloat16(x), __float2bfloat16(y)};
    return *(uint32_t*)&p;
}
__device__ __forceinline__ void split1(float v, __nv_bfloat16& h, __nv_bfloat16& l) {
    h = __float2bfloat16(v);
    l = __float2bfloat16(v - __bfloat162float(h));
}
__device__ __forceinline__ void cp16(uint32_t dst, const void* src, bool pred) {
    int sz = pred ? 16 : 0;
    asm volatile("cp.async.cg.shared.global [%0], [%1], 16, %2;"
                 :: "r"(dst), "l"(src), "r"(sz));
}
__device__ __forceinline__ void cp_commit() {
    asm volatile("cp.async.commit_group;");
}
__device__ __forceinline__ void cp_wait1() {
    asm volatile("cp.async.wait_group 1;");
}

extern __shared__ unsigned char dynsm[];

// ===========================================================================
// Pre-split: x, w_qkv, w_proj -> bf16 hi/lo
// ===========================================================================
__global__ __launch_bounds__(256) void split_all(
    const float* __restrict__ x,
    const float* __restrict__ wq,
    const float* __restrict__ wp)
{
    long i = ((long)blockIdx.x * 256 + threadIdx.x) * 4;
    const float* src;
    __nv_bfloat16 *dh, *dl;
    long o;
    if (i < NX)                 { src = x;  dh = g_xh;  dl = g_xl;  o = i; }
    else if (i < NX + NWQ)      { src = wq; dh = g_wqh; dl = g_wql; o = i - NX; }
    else if (i < NX + NWQ + NWP){ src = wp; dh = g_wph; dl = g_wpl; o = i - NX - NWQ; }
    else return;
    float4 f = *(const float4*)(src + o);
    __nv_bfloat16 h0, h1, h2, h3, l0, l1, l2, l3;
    split1(f.x, h0, l0); split1(f.y, h1, l1);
    split1(f.z, h2, l2); split1(f.w, h3, l3);
    __nv_bfloat162 ph0{h0, h1}, ph1{h2, h3}, pl0{l0, l1}, pl1{l2, l3};
    *(uint2*)(dh + o) = make_uint2(*(uint32_t*)&ph0, *(uint32_t*)&ph1);
    *(uint2*)(dl + o) = make_uint2(*(uint32_t*)&pl0, *(uint32_t*)&pl1);
}

// ===========================================================================
// Split-bf16 tensor GEMM, cp.async 3-stage pipeline (R12-proven: 113.7KB
// smem -> 2 CTAs/SM co-resident; proj measured 92us @ tensor=59%).
// ===========================================================================
#define APITCH 40
#define BPITCH 136
#define STAGE_ELEMS (128 * APITCH * 2 + 32 * BPITCH * 2)
#define STAGE_BYTES (STAGE_ELEMS * 2)      // 37888
#define NSTAGE 3
#define GEMM_SMEM (NSTAGE * STAGE_BYTES)   // 113664 -> 2 CTA/SM

template <int EPI>
__global__ __launch_bounds__(256) void gemm_pipe(
    const float* __restrict__ bias,
    float* __restrict__ out)
{
    constexpr int LDB = EPI ? Cc : QKVN;
    constexpr int NT  = KDIM / 32;  // 24
    const __nv_bfloat16* Ah = EPI ? g_aoh : g_xh;
    const __nv_bfloat16* Al = EPI ? g_aol : g_xl;
    const __nv_bfloat16* Bh = EPI ? g_wph : g_wqh;
    const __nv_bfloat16* Bl = EPI ? g_wpl : g_wql;

    const int tid  = threadIdx.x;
    const int lane = tid & 31, warp = tid >> 5;
    const int rowBase = blockIdx.y * 128;
    const int colBase = blockIdx.x * 128;
    const int wm0 = (warp >> 2) * 64;
    const int wn0 = (warp & 3) * 32;
    const uint32_t smemBase = smem_u32(dynsm);

    auto issue_tile = [&](int tile, int stage) {
        const int k0 = tile * 32;
        const uint32_t sb = smemBase + stage * STAGE_BYTES;
#pragma unroll
        for (int rep = 0; rep < 2; rep++) {
            const int g = tid + rep * 256;
            const int row = g >> 2, kc = g & 3;
            const int gr = rowBase + row;
            const bool ok = gr < MM;
            const long so = (long)(ok ? gr : 0) * KDIM + k0 + kc * 8;
            const uint32_t d = sb + (row * APITCH + kc * 8) * 2;
            cp16(d,                    Ah + so, ok);
            cp16(d + 128 * APITCH * 2, Al + so, ok);
        }
#pragma unroll
        for (int rep = 0; rep < 2; rep++) {
            const int g = tid + rep * 256;
            const int krow = g >> 4, nc = g & 15;
            const long so = (long)(k0 + krow) * LDB + colBase + nc * 8;
            const uint32_t d = sb + (256 * APITCH + krow * BPITCH + nc * 8) * 2;
            cp16(d,                   Bh + so, true);
            cp16(d + 32 * BPITCH * 2, Bl + so, true);
        }
        cp_commit();
    };

    float acc[4][4][4];
#pragma unroll
    for (int mi = 0; mi < 4; mi++)
#pragma unroll
        for (int j = 0; j < 4; j++)
#pragma unroll
            for (int r = 0; r < 4; r++) acc[mi][j][r] = 0.f;

    const int aOff = (wm0 + (lane & 15)) * (APITCH * 2) + (lane >> 4) * 16;
    const int bOff = (lane & 15) * (BPITCH * 2) + (wn0 + ((lane >> 4) << 3)) * 2;

    issue_tile(0, 0);
    issue_tile(1, 1);

#pragma unroll 1
    for (int t = 0; t < NT; t++) {
        cp_wait1();
        __syncthreads();
        if (t + 2 < NT) issue_tile(t + 2, (t + 2) % NSTAGE);
        else cp_commit();   // keep group accounting uniform

        const uint32_t base = smemBase + (t % NSTAGE) * STAGE_BYTES;
        const uint32_t aHiB = base + aOff;
        const uint32_t aLoB = aHiB + 128 * APITCH * 2;
        const uint32_t bHiB = base + 256 * APITCH * 2 + bOff;
        const uint32_t bLoB = bHiB + 32 * BPITCH * 2;

#pragma unroll
        for (int ks = 0; ks < 2; ks++) {
            uint32_t ah[4][4], al[4][4], bh[2][4], bl[2][4];
#pragma unroll
            for (int mi = 0; mi < 4; mi++) {
                ldsm4(ah[mi], aHiB + mi * (16 * APITCH * 2) + ks * 32);
                ldsm4(al[mi], aLoB + mi * (16 * APITCH * 2) + ks * 32);
            }
#pragma unroll
            for (int nb = 0; nb < 2; nb++) {
                ldsm4t(bh[nb], bHiB + nb * 32 + ks * (16 * BPITCH * 2));
                ldsm4t(bl[nb], bLoB + nb * 32 + ks * (16 * BPITCH * 2));
            }
#pragma unroll
            for (int mi = 0; mi < 4; mi++)
#pragma unroll
                for (int j = 0; j < 4; j++) {
                    const int nb = j >> 1, hf = (j & 1) * 2;
                    mma16816(acc[mi][j], ah[mi], bh[nb][hf], bh[nb][hf + 1]);
                    mma16816(acc[mi][j], ah[mi], bl[nb][hf], bl[nb][hf + 1]);
                    mma16816(acc[mi][j], al[mi], bh[nb][hf], bh[nb][hf + 1]);
                }
        }
    }

    // ---- epilogue ----
#pragma unroll
    for (int mi = 0; mi < 4; mi++) {
        const int r0 = wm0 + mi * 16 + (lane >> 2);
#pragma unroll
        for (int half = 0; half < 2; half++) {
            const int gr = rowBase + r0 + half * 8;
            if (gr >= MM) continue;
            if (EPI == 0) {
                const int bidx = gr / Nn, n = gr % Nn;
#pragma unroll
                for (int j = 0; j < 4; j++) {
                    const int c0 = wn0 + j * 8 + (lane & 3) * 2;
#pragma unroll
                    for (int e = 0; e < 2; e++) {
                        const int gc = colBase + c0 + e;
                        float v = acc[mi][j][half * 2 + e] + bias[gc];
                        const int which = gc / Cc;
                        const int cc = gc % Cc;
                        const int h = cc >> 6, d = cc & 63;
                        const long base = (((long)bidx * Hh + h) * Nn + n) * Dd + d;
                        __nv_bfloat16 hh, ll;
                        split1(v, hh, ll);
                        if (which == 0)      { g_qh[base] = hh; g_ql[base] = ll; }
                        else if (which == 1) { g_kh[base] = hh; g_kl[base] = ll; }
                        else                 { g_vh[base] = hh; g_vl[base] = ll; }
                    }
                }
            } else {
#pragma unroll
                for (int j = 0; j < 4; j++) {
                    const int c0 = wn0 + j * 8 + (lane & 3) * 2;
                    const int gc = colBase + c0;
                    float2 v2 = make_float2(acc[mi][j][half * 2 + 0] + bias[gc],
                                            acc[mi][j][half * 2 + 1] + bias[gc + 1]);
                    *(float2*)&out[(long)gr * Cc + gc] = v2;
                }
            }
        }
    }
}

// ===========================================================================
// Tensor-core flash attention, cp.async double-buffered K/V chunks (R14).
// Smem: Q 36864 + 2 chunk bufs (36864 each) = 110592 B.
// ===========================================================================
#define QT 128
#define KT 64
#define NQT ((Nn + QT - 1) / QT)   // 5
#define NKT ((Nn + KT - 1) / KT)   // 10
#define QP 72
#define QREG_BYTES (2 * QT * QP * 2)   // 36864
#define CHUNK_BYTES (4 * KT * QP * 2)  // 36864
#define ATTN_SMEM (QREG_BYTES + 2 * CHUNK_BYTES)  // 110592

__global__ __launch_bounds__(256) void attn_mma(
    const float* __restrict__ aw,
    float* __restrict__ patch)
{
    __nv_bfloat16* sm = (__nv_bfloat16*)dynsm;
    __nv_bfloat16* Qhi = sm;
    __nv_bfloat16* Qlo = sm + QT * QP;

    const int bh = blockIdx.y;
    const int b  = bh / Hh;
    const int h  = bh % Hh;
    const int qt = blockIdx.x;
    const int n0 = qt * QT;
    const int NQ = min(QT, Nn - n0);

    const int tid  = threadIdx.x;
    const int lane = tid & 31, warp = tid >> 5;
    const uint32_t smBase = smem_u32(dynsm);

    auto issue_chunk = [&](int ch) {
        if (ch >= NKT) { cp_commit(); return; }
        const int kc0 = ch * KT;
        const uint32_t bb = smBase + QREG_BYTES + (ch & 1) * CHUNK_BYTES;
#pragma unroll
        for (int rep = 0; rep < 2; rep++) {
            const int g = tid + rep * 256;
            const int c = g >> 3, q = g & 7;
            const bool ok = (kc0 + c) < Nn;
            const long gb = ((long)bh * Nn + (ok ? kc0 + c : 0)) * Dd + q * 8;
            const uint32_t de = (uint32_t)(c * QP + q * 8) * 2;
            cp16(bb + de,         g_kh + gb, ok);
            cp16(bb + 9216 + de,  g_kl + gb, ok);
            cp16(bb + 18432 + de, g_vh + gb, ok);
            cp16(bb + 27648 + de, g_vl + gb, ok);
        }
        cp_commit();
    };

    // ---- stage Q tile (hi/lo straight copy) ----
    {
        const int r = tid >> 1;
        const int half = tid & 1;
        const bool valid = (r < NQ);
        const long gb = ((long)bh * Nn + n0 + (valid ? r : 0)) * Dd;
        const uint4* sh = (const uint4*)(g_qh + gb) + half * 4;
        const uint4* sl = (const uint4*)(g_ql + gb) + half * 4;
        uint4* dh = (uint4*)(Qhi + r * QP + half * 32);
        uint4* dl = (uint4*)(Qlo + r * QP + half * 32);
        const uint4 z = make_uint4(0, 0, 0, 0);
#pragma unroll
        for (int i = 0; i < 4; i++) {
            dh[i] = valid ? sh[i] : z;
            dl[i] = valid ? sl[i] : z;
        }
    }
    issue_chunk(0);
    __syncthreads();

    // ---- Q fragments to registers ----
    uint32_t qh[4][4], ql[4][4];
    {
        const uint32_t qLane = ((warp << 4) + (lane & 15)) * (QP * 2) + (lane >> 4) * 16;
        const uint32_t QhiB = smem_u32(Qhi) + qLane;
        const uint32_t QloB = smem_u32(Qlo) + qLane;
#pragma unroll
        for (int ks = 0; ks < 4; ks++) {
            ldsm4(qh[ks], QhiB + ks * 32);
            ldsm4(ql[ks], QloB + ks * 32);
        }
    }

    float m_lo = -1e30f, m_hi = -1e30f, l_lo = 0.f, l_hi = 0.f;
    float o[8][4];
#pragma unroll
    for (int nt = 0; nt < 8; nt++)
#pragma unroll
        for (int e = 0; e < 4; e++) o[nt][e] = 0.f;

    const uint32_t fragLane = (lane & 15) * (QP * 2) + (lane >> 4) * 16;
    const int cbase = 2 * (lane & 3);
    const bool clsLane = (qt == 0) && (warp == 0) && ((lane >> 2) == 0);

#pragma unroll 1
    for (int ch = 0; ch < NKT; ch++) {
        const int kc0 = ch * KT;
        const int KC  = min(KT, Nn - kc0);

        issue_chunk(ch + 1);
        cp_wait1();
        __syncthreads();

        const uint32_t bb = smBase + QREG_BYTES + (ch & 1) * CHUNK_BYTES;
        const uint32_t KhiB = bb + fragLane;
        const uint32_t KloB = bb + 9216 + fragLane;
        const uint32_t VhiB = bb + 18432 + fragLane;
        const uint32_t VloB = bb + 27648 + fragLane;

        // ---- S = Q·K^T ----
        float s[8][4];
#pragma unroll
        for (int nt = 0; nt < 8; nt++)
#pragma unroll
            for (int e = 0; e < 4; e++) s[nt][e] = 0.f;

#pragma unroll
        for (int ks = 0; ks < 4; ks++)
#pragma unroll
            for (int g = 0; g < 4; g++) {
                uint32_t kh[4], kl[4];
                const uint32_t off = g * (16 * QP * 2) + ks * 32;
                ldsm4(kh, KhiB + off);
                ldsm4(kl, KloB + off);
                mma16816(s[2 * g],     qh[ks], kh[0], kh[2]);
                mma16816(s[2 * g],     qh[ks], kl[0], kl[2]);
                mma16816(s[2 * g],     ql[ks], kh[0], kh[2]);
                mma16816(s[2 * g + 1], qh[ks], kh[1], kh[3]);
                mma16816(s[2 * g + 1], qh[ks], kl[1], kl[3]);
                mma16816(s[2 * g + 1], ql[ks], kh[1], kh[3]);
            }

        // ---- scale + mask ----
#pragma unroll
        for (int nt = 0; nt < 8; nt++)
#pragma unroll
            for (int e = 0; e < 4; e++) {
                const int c = nt * 8 + cbase + (e & 1);
                float sv = s[nt][e] * SCALEF;
                s[nt][e] = (c < KC) ? sv : -1e30f;
            }

        // ---- CLS row: patch emit + reweight ----
        if (clsLane) {
#pragma unroll
            for (int nt = 0; nt < 8; nt++)
#pragma unroll
                for (int e = 0; e < 2; e++) {
                    const int mg = kc0 + nt * 8 + cbase + e;
                    if (mg >= 1 && mg < Nn) {
                        const float sv = s[nt][e];
                        patch[(long)bh * NPATCH + mg - 1] = sv;
                        const float w = aw[(long)b * NPATCH + mg - 1];
                        s[nt][e] = sv * (w * ALPHAF + (1.0f - ALPHAF));
                    }
                }
        }

        // ---- online softmax ----
        {
            float cmlo = -1e30f, cmhi = -1e30f;
#pragma unroll
            for (int nt = 0; nt < 8; nt++) {
                cmlo = fmaxf(cmlo, fmaxf(s[nt][0], s[nt][1]));
                cmhi = fmaxf(cmhi, fmaxf(s[nt][2], s[nt][3]));
            }
#pragma unroll
            for (int off = 1; off <= 2; off <<= 1) {
                cmlo = fmaxf(cmlo, __shfl_xor_sync(0xffffffffu, cmlo, off));
                cmhi = fmaxf(cmhi, __shfl_xor_sync(0xffffffffu, cmhi, off));
            }
            const float mnlo = fmaxf(m_lo, cmlo);
            const float mnhi = fmaxf(m_hi, cmhi);
            const float flo = __expf(m_lo - mnlo);
            const float fhi = __expf(m_hi - mnhi);
            float rslo = 0.f, rshi = 0.f;
#pragma unroll
            for (int nt = 0; nt < 8; nt++) {
                s[nt][0] = __expf(s[nt][0] - mnlo); rslo += s[nt][0];
                s[nt][1] = __expf(s[nt][1] - mnlo); rslo += s[nt][1];
                s[nt][2] = __expf(s[nt][2] - mnhi); rshi += s[nt][2];
                s[nt][3] = __expf(s[nt][3] - mnhi); rshi += s[nt][3];
            }
#pragma unroll
            for (int off = 1; off <= 2; off <<= 1) {
                rslo += __shfl_xor_sync(0xffffffffu, rslo, off);
                rshi += __shfl_xor_sync(0xffffffffu, rshi, off);
            }
            l_lo = l_lo * flo + rslo;  m_lo = mnlo;
            l_hi = l_hi * fhi + rshi;  m_hi = mnhi;
#pragma unroll
            for (int nt = 0; nt < 8; nt++) {
                o[nt][0] *= flo; o[nt][1] *= flo;
                o[nt][2] *= fhi; o[nt][3] *= fhi;
            }
        }

        // ---- O += P·V ----
#pragma unroll
        for (int kt = 0; kt < 4; kt++) {
            uint32_t pa_h[4], pa_l[4];
            {
                float lx, ly;
                pa_h[0] = pack_hi(s[2 * kt][0],     s[2 * kt][1],     lx, ly);
                pa_l[0] = pack_bf2(lx, ly);
                pa_h[1] = pack_hi(s[2 * kt][2],     s[2 * kt][3],     lx, ly);
                pa_l[1] = pack_bf2(lx, ly);
                pa_h[2] = pack_hi(s[2 * kt + 1][0], s[2 * kt + 1][1], lx, ly);
                pa_l[2] = pack_bf2(lx, ly);
                pa_h[3] = pack_hi(s[2 * kt + 1][2], s[2 * kt + 1][3], lx, ly);
                pa_l[3] = pack_bf2(lx, ly);
            }
#pragma unroll
            for (int g = 0; g < 4; g++) {
                uint32_t vh[4], vl[4];
                const uint32_t off = kt * (16 * QP * 2) + g * 32;
                ldsm4t(vh, VhiB + off);
                ldsm4t(vl, VloB + off);
                mma16816(o[2 * g],     pa_h, vh[0], vh[1]);
                mma16816(o[2 * g],     pa_h, vl[0], vl[1]);
                mma16816(o[2 * g],     pa_l, vh[0], vh[1]);
                mma16816(o[2 * g + 1], pa_h, vh[2], vh[3]);
                mma16816(o[2 * g + 1], pa_h, vl[2], vl[3]);
                mma16816(o[2 * g + 1], pa_l, vh[2], vh[3]);
            }
        }
        __syncthreads();
    }

    // ---- write O normalized as bf16 hi/lo ----
    {
        const int rlo = warp * 16 + (lane >> 2);
        const float invlo = 1.0f / l_lo;
        const float invhi = 1.0f / l_hi;
#pragma unroll
        for (int nt = 0; nt < 8; nt++) {
            const int d = h * Dd + nt * 8 + cbase;
            if (rlo < NQ) {
                const long base = ((long)(b * Nn + n0 + rlo)) * Cc + d;
                float a0 = o[nt][0] * invlo, a1 = o[nt][1] * invlo;
                float lx, ly;
                uint32_t hh = pack_hi(a0, a1, lx, ly);
                *(uint32_t*)&g_aoh[base] = hh;
                *(uint32_t*)&g_aol[base] = pack_bf2(lx, ly);
            }
            if (rlo + 8 < NQ) {
                const long base = ((long)(b * Nn + n0 + rlo + 8)) * Cc + d;
                float a0 = o[nt][2] * invhi, a1 = o[nt][3] * invhi;
                float lx, ly;
                uint32_t hh = pack_hi(a0, a1, lx, ly);
                *(uint32_t*)&g_aoh[base] = hh;
                *(uint32_t*)&g_aol[base] = pack_bf2(lx, ly);
            }
        }
    }
}

// ---------------------------------------------------------------------------
extern "C" void kernel_launch(void* const* d_in, const int* in_sizes, int n_in,
                              void* d_out, int out_size)
{
    const float* x      = (const float*)d_in[0];
    const float* aw     = (const float*)d_in[1];
    const float* w_qkv  = (const float*)d_in[2];
    const float* b_qkv  = (const float*)d_in[3];
    const float* w_proj = (const float*)d_in[4];
    const float* b_proj = (const float*)d_in[5];

    float* out   = (float*)d_out;
    float* patch = out + (long)Bb * Nn * Cc;

    // >48KB dynamic smem: opt in every call (no static guards).
    cudaFuncSetAttribute(gemm_pipe<0>, cudaFuncAttributeMaxDynamicSharedMemorySize, GEMM_SMEM);
    cudaFuncSetAttribute(gemm_pipe<1>, cudaFuncAttributeMaxDynamicSharedMemorySize, GEMM_SMEM);
    cudaFuncSetAttribute(attn_mma, cudaFuncAttributeMaxDynamicSharedMemorySize, ATTN_SMEM);

    const long nsplit = ((long)NX + NWQ + NWP) / 4;
    split_all<<<(unsigned)((nsplit + 255) / 256), 256>>>(x, w_qkv, w_proj);

    dim3 gq(QKVN / 128, (MM + 127) / 128);     // 18 x 73
    gemm_pipe<0><<<gq, 256, GEMM_SMEM>>>(b_qkv, nullptr);

    dim3 ga(NQT, Bb * Hh);                     // 5 x 192
    attn_mma<<<ga, 256, ATTN_SMEM>>>(aw, patch);

    dim3 gp(Cc / 128, (MM + 127) / 128);       // 6 x 73
    gemm_pipe<1><<<gp, 256, GEMM_SMEM>>>(b_proj, out);
}